// round 9
// baseline (speedup 1.0000x reference)
#include <cuda_runtime.h>
#include <cuda_bf16.h>
#include <math.h>
#include <stdint.h>

// Problem constants (shapes fixed by the dataset).
#define DIM   256
#define MAXN  100000
#define MAXE  800000
#define SCANB 1024
#define MAXBLK 128          // >= ceil(MAXN/SCANB) = 98

// -------- device-global scratch (allocation-free workaround) --------
__device__ float g_support[MAXN * DIM];   // x @ W
__device__ int   g_counts[MAXN];
__device__ int   g_scan[MAXN];
__device__ int   g_rowptr[MAXN + 1];
__device__ int   g_cursor[MAXN];
__device__ int   g_bsum[MAXBLK];
__device__ int   g_esrc[MAXE];
__device__ float g_eval[MAXE];

// ---------------- CSR construction ----------------
__global__ void k_zero_counts(int n) {
    int i = blockIdx.x * blockDim.x + threadIdx.x;
    if (i < n) g_counts[i] = 0;
}

__global__ void k_hist(const int* __restrict__ dst, int E) {
    int e = blockIdx.x * blockDim.x + threadIdx.x;
    if (e < E) atomicAdd(&g_counts[dst[e]], 1);
}

__global__ void k_scan_block(int n) {
    __shared__ int s[SCANB];
    int t = threadIdx.x;
    int gid = blockIdx.x * SCANB + t;
    int v = (gid < n) ? g_counts[gid] : 0;
    s[t] = v;
    __syncthreads();
    #pragma unroll
    for (int off = 1; off < SCANB; off <<= 1) {
        int x = (t >= off) ? s[t - off] : 0;
        __syncthreads();
        s[t] += x;
        __syncthreads();
    }
    if (gid < n) g_scan[gid] = s[t];
    if (t == SCANB - 1) g_bsum[blockIdx.x] = s[t];
}

__global__ void k_scan_sums(int nb) {
    __shared__ int s[MAXBLK];
    int t = threadIdx.x;                 // 128 threads
    int v = (t < nb) ? g_bsum[t] : 0;
    s[t] = v;
    __syncthreads();
    #pragma unroll
    for (int off = 1; off < MAXBLK; off <<= 1) {
        int x = (t >= off) ? s[t - off] : 0;
        __syncthreads();
        s[t] += x;
        __syncthreads();
    }
    if (t < nb) g_bsum[t] = s[t] - v;    // exclusive
}

__global__ void k_finalize_rowptr(int n) {
    int i = blockIdx.x * blockDim.x + threadIdx.x;
    if (i < n) {
        g_rowptr[i + 1] = g_scan[i] + g_bsum[i >> 10];
        int rp0 = (i == 0) ? 0 : (g_scan[i - 1] + g_bsum[(i - 1) >> 10]);
        g_cursor[i] = rp0;
        if (i == 0) g_rowptr[0] = 0;
    }
}

__global__ void k_fill(const int* __restrict__ dst, const int* __restrict__ src,
                       const float* __restrict__ av, const float* __restrict__ aw, int E) {
    int e = blockIdx.x * blockDim.x + threadIdx.x;
    if (e < E) {
        int d = dst[e];
        int p = atomicAdd(&g_cursor[d], 1);
        g_esrc[p] = src[e];
        g_eval[p] = av[e] + aw[e];
    }
}

// ---------------- GEMM: support = x @ W  (3xBF16 + ldmatrix) ----------------
// 128x128 block tile, BK=32, 256 threads = 8 warps in 2(M) x 4(N).
// Warp tile 64x32 = 4x4 m16n8k16 sub-tiles. Fragments via ldmatrix.x4.
// A smem: [m][k] bf16x2 rows (16 u32 data, pitch 20). B smem: [n][k] rows,
// 16B chunks XOR-swizzled by (n>>2)&3 for conflict-free stores + LDSM.

__device__ __forceinline__ uint32_t smem_u32(const void* p) {
    uint32_t a;
    asm("{ .reg .u64 t; cvta.to.shared.u64 t, %1; cvt.u32.u64 %0, t; }" : "=r"(a) : "l"(p));
    return a;
}
__device__ __forceinline__ uint32_t pack_bf16(float a, float b) {
    __nv_bfloat162 h = __floats2bfloat162_rn(a, b);
    return *reinterpret_cast<uint32_t*>(&h);
}
__device__ __forceinline__ float bf16_hi_f(float a) {
    return __bfloat162float(__float2bfloat16_rn(a));
}

__device__ __forceinline__ void ldsm_x4(uint32_t& r0, uint32_t& r1, uint32_t& r2, uint32_t& r3,
                                        uint32_t addr) {
    asm volatile("ldmatrix.sync.aligned.m8n8.x4.shared.b16 {%0,%1,%2,%3}, [%4];"
                 : "=r"(r0), "=r"(r1), "=r"(r2), "=r"(r3) : "r"(addr));
}

__device__ __forceinline__ void mma_bf16(float c[4], uint32_t a0, uint32_t a1,
                                         uint32_t a2, uint32_t a3,
                                         uint32_t b0, uint32_t b1) {
    asm volatile(
        "mma.sync.aligned.m16n8k16.row.col.f32.bf16.bf16.f32 "
        "{%0,%1,%2,%3}, {%4,%5,%6,%7}, {%8,%9}, {%0,%1,%2,%3};"
        : "+f"(c[0]), "+f"(c[1]), "+f"(c[2]), "+f"(c[3])
        : "r"(a0), "r"(a1), "r"(a2), "r"(a3), "r"(b0), "r"(b1));
}

#define GBM 128
#define GBN 128
#define GBK 32
#define APITCH 20     // u32 per A row (16 data + 4 pad); 8-row stride hits all banks
#define BPITCH 20     // u32 per B row

__global__ __launch_bounds__(256) void k_gemm_bf16(const float* __restrict__ X,
                                                   const float* __restrict__ W, int Nrows) {
    __shared__ uint32_t Ash[GBM][APITCH];   // [m][kpair] hi
    __shared__ uint32_t Asl[GBM][APITCH];   // lo
    __shared__ uint32_t Bsh[GBN][BPITCH];   // [n][kpair, chunk-swizzled] hi
    __shared__ uint32_t Bsl[GBN][BPITCH];   // lo

    const int tid  = threadIdx.x;
    const int lane = tid & 31;
    const int wid  = tid >> 5;
    const int warp_m = wid >> 2;        // 0..1
    const int warp_n = wid & 3;         // 0..3
    const int block_m = blockIdx.x * GBM;
    const int block_n = blockIdx.y * GBN;

    float acc[4][4][4];
    #pragma unroll
    for (int i = 0; i < 4; i++)
        #pragma unroll
        for (int j = 0; j < 4; j++)
            #pragma unroll
            for (int r = 0; r < 4; r++) acc[i][j][r] = 0.0f;

    // ---- Precomputed LDSM lane addressing ----
    // A: lanes 0-15 -> row m0+(lane&15), chunk +0; lanes 16-31 -> same row, chunk +1.
    const uint32_t a_hi_base = smem_u32(&Ash[0][0]);
    const uint32_t a_lo_base = smem_u32(&Asl[0][0]);
    const uint32_t a_row = (uint32_t)(warp_m * 64 + (lane & 15)) * (APITCH * 4);
    const uint32_t a_ch  = (uint32_t)(lane >> 4) * 16;          // bytes
    // B: n = n0 + (lane&7) + ((lane>>4)&1)*8 ; chunk add = (lane>>3)&1.
    const uint32_t b_hi_base = smem_u32(&Bsh[0][0]);
    const uint32_t b_lo_base = smem_u32(&Bsl[0][0]);
    const int b_nl  = (lane & 7) + ((lane >> 4) & 1) * 8;       // 0..15 within 16-row pair
    const int b_cha = (lane >> 3) & 1;                          // chunk +0/+1

    for (int k0 = 0; k0 < DIM; k0 += GBK) {
        // ---- Load A tile: 128 rows x 32 k = 1024 float4, 4 per thread ----
        #pragma unroll
        for (int l = 0; l < 4; l++) {
            int idx = tid + l * 256;        // 0..1023
            int r   = idx >> 3;             // 8 float4 per row
            int k4  = idx & 7;
            int grow = block_m + r;
            float4 a = make_float4(0.f, 0.f, 0.f, 0.f);
            if (grow < Nrows)
                a = *reinterpret_cast<const float4*>(&X[(size_t)grow * DIM + k0 + k4 * 4]);
            float hx = bf16_hi_f(a.x), hy = bf16_hi_f(a.y), hz = bf16_hi_f(a.z), hw = bf16_hi_f(a.w);
            *reinterpret_cast<uint2*>(&Ash[r][2 * k4]) =
                make_uint2(pack_bf16(hx, hy), pack_bf16(hz, hw));
            *reinterpret_cast<uint2*>(&Asl[r][2 * k4]) =
                make_uint2(pack_bf16(a.x - hx, a.y - hy), pack_bf16(a.z - hz, a.w - hw));
        }
        // ---- Load B tile: W[k0..k0+31][block_n..+127] -> Bs[n][k] hi/lo ----
        // Warp covers kp(l&7 | (w&1)<<3 ? no: per-iter mapping below) chosen for
        // conflict-free swizzled stores: lanes span 8 kp x 4 n4.
        #pragma unroll
        for (int l = 0; l < 2; l++) {
            int idx = tid + l * 256;        // 0..511
            int li  = idx & 31;
            int w8  = idx >> 5;             // 0..15
            int kp  = (li & 7) | ((w8 & 1) << 3);        // 0..15
            int n4  = (li >> 3) | ((w8 >> 1) << 2);      // 0..31
            int k   = k0 + 2 * kp;
            float4 w0 = *reinterpret_cast<const float4*>(&W[(size_t)k * DIM + block_n + n4 * 4]);
            float4 w1 = *reinterpret_cast<const float4*>(&W[(size_t)(k + 1) * DIM + block_n + n4 * 4]);
            float a0[4] = {w0.x, w0.y, w0.z, w0.w};
            float a1[4] = {w1.x, w1.y, w1.z, w1.w};
            int c = kp >> 2, r = kp & 3;
            int col = ((c ^ (n4 & 3)) << 2) | r;         // swizzled u32 column
            #pragma unroll
            for (int j = 0; j < 4; j++) {
                int n = n4 * 4 + j;
                float h0 = bf16_hi_f(a0[j]);
                float h1 = bf16_hi_f(a1[j]);
                Bsh[n][col] = pack_bf16(h0, h1);
                Bsl[n][col] = pack_bf16(a0[j] - h0, a1[j] - h1);
            }
        }
        __syncthreads();

        #pragma unroll
        for (int si = 0; si < 2; si++) {    // two k16 sub-iters per BK=32
            // A fragments via ldmatrix.x4 (r0..r3 = a0..a3 exactly)
            uint32_t fah[4][4], fal[4][4];
            #pragma unroll
            for (int mt = 0; mt < 4; mt++) {
                uint32_t off = a_row + (uint32_t)(mt * 16) * (APITCH * 4) + a_ch + (uint32_t)si * 32;
                ldsm_x4(fah[mt][0], fah[mt][1], fah[mt][2], fah[mt][3], a_hi_base + off);
                ldsm_x4(fal[mt][0], fal[mt][1], fal[mt][2], fal[mt][3], a_lo_base + off);
            }
            // B fragments: one x4 covers two nt tiles (b0,b1) each
            uint32_t fbh[4][2], fbl[4][2];
            #pragma unroll
            for (int ntp = 0; ntp < 2; ntp++) {
                int n = warp_n * 32 + ntp * 16 + b_nl;
                uint32_t chunk = (uint32_t)((2 * si + b_cha) ^ ((n >> 2) & 3));
                uint32_t off = (uint32_t)n * (BPITCH * 4) + chunk * 16;
                ldsm_x4(fbh[2 * ntp][0], fbh[2 * ntp][1], fbh[2 * ntp + 1][0], fbh[2 * ntp + 1][1],
                        b_hi_base + off);
                ldsm_x4(fbl[2 * ntp][0], fbl[2 * ntp][1], fbl[2 * ntp + 1][0], fbl[2 * ntp + 1][1],
                        b_lo_base + off);
            }
            #pragma unroll
            for (int mt = 0; mt < 4; mt++)
                #pragma unroll
                for (int nt = 0; nt < 4; nt++) {
                    mma_bf16(acc[mt][nt], fal[mt][0], fal[mt][1], fal[mt][2], fal[mt][3],
                             fbh[nt][0], fbh[nt][1]);
                    mma_bf16(acc[mt][nt], fah[mt][0], fah[mt][1], fah[mt][2], fah[mt][3],
                             fbl[nt][0], fbl[nt][1]);
                    mma_bf16(acc[mt][nt], fah[mt][0], fah[mt][1], fah[mt][2], fah[mt][3],
                             fbh[nt][0], fbh[nt][1]);
                }
        }
        __syncthreads();
    }

    // Epilogue: write 64x32 warp tile
    const int g  = lane >> 2;
    const int tg = lane & 3;
    #pragma unroll
    for (int mt = 0; mt < 4; mt++) {
        int r0 = block_m + warp_m * 64 + mt * 16 + g;
        #pragma unroll
        for (int nt = 0; nt < 4; nt++) {
            int c = block_n + warp_n * 32 + nt * 8 + 2 * tg;
            if (r0 < Nrows)
                *reinterpret_cast<float2*>(&g_support[(size_t)r0 * DIM + c]) =
                    make_float2(acc[mt][nt][0], acc[mt][nt][1]);
            if (r0 + 8 < Nrows)
                *reinterpret_cast<float2*>(&g_support[(size_t)(r0 + 8) * DIM + c]) =
                    make_float2(acc[mt][nt][2], acc[mt][nt][3]);
        }
    }
}

// ---------------- SpMM + fused L2 normalize ----------------
__global__ __launch_bounds__(DIM) void k_spmm_norm(float* __restrict__ out, int n) {
    const int row = blockIdx.x;
    if (row >= n) return;
    const int t = threadIdx.x;

    const int beg = g_rowptr[row];
    const int end = g_rowptr[row + 1];

    float acc0 = 0.0f, acc1 = 0.0f;
    int e = beg;
    for (; e + 1 < end; e += 2) {
        int   s0 = __ldg(&g_esrc[e]);
        int   s1 = __ldg(&g_esrc[e + 1]);
        float v0 = __ldg(&g_eval[e]);
        float v1 = __ldg(&g_eval[e + 1]);
        acc0 = fmaf(v0, g_support[(size_t)s0 * DIM + t], acc0);
        acc1 = fmaf(v1, g_support[(size_t)s1 * DIM + t], acc1);
    }
    if (e < end) {
        int   s0 = __ldg(&g_esrc[e]);
        float v0 = __ldg(&g_eval[e]);
        acc0 = fmaf(v0, g_support[(size_t)s0 * DIM + t], acc0);
    }
    float acc = acc0 + acc1;

    __shared__ float red[DIM];
    red[t] = acc * acc;
    __syncthreads();
    #pragma unroll
    for (int s = DIM / 2; s >= 32; s >>= 1) {
        if (t < s) red[t] += red[t + s];
        __syncthreads();
    }
    if (t < 32) {
        float w = red[t];
        #pragma unroll
        for (int o = 16; o > 0; o >>= 1) w += __shfl_down_sync(0xFFFFFFFF, w, o);
        if (t == 0) red[0] = w;
    }
    __syncthreads();
    float ss = red[0];

    float norm  = sqrtf(ss);
    float denom = fmaxf(norm, 1e-12f);
    out[(size_t)row * DIM + t] = acc / denom;
}

// ---------------- launch ----------------
extern "C" void kernel_launch(void* const* d_in, const int* in_sizes, int n_in,
                              void* d_out, int out_size) {
    const float* x  = (const float*)d_in[0];   // [N, 256]
    const float* W  = (const float*)d_in[1];   // [256, 256]
    const float* av = (const float*)d_in[2];   // [E]
    const float* aw = (const float*)d_in[3];   // [E]
    const int*   ei = (const int*)  d_in[4];   // [2, E]: dst row, then src row
    float* out = (float*)d_out;

    int N = in_sizes[0] / DIM;
    int E = in_sizes[2];
    const int* dst = ei;
    const int* src = ei + E;

    int nb = (N + SCANB - 1) / SCANB;

    // GEMM (independent of CSR build)
    dim3 ggrid((N + GBM - 1) / GBM, DIM / GBN);
    k_gemm_bf16<<<ggrid, 256>>>(x, W, N);

    // CSR build
    k_zero_counts<<<(N + 255) / 256, 256>>>(N);
    k_hist<<<(E + 255) / 256, 256>>>(dst, E);
    k_scan_block<<<nb, SCANB>>>(N);
    k_scan_sums<<<1, MAXBLK>>>(nb);
    k_finalize_rowptr<<<(N + 255) / 256, 256>>>(N);
    k_fill<<<(E + 255) / 256, 256>>>(dst, src, av, aw, E);

    // Aggregate + normalize
    k_spmm_norm<<<N, DIM>>>(out, N);
}